// round 9
// baseline (speedup 1.0000x reference)
#include <cuda_runtime.h>
#include <cstdint>

#define N_NODES 100000
#define CH      128
#define N_REL   16
#define N_EDGES 200000
#define NW      17                        /* self + 16 relations */
#define NT      ((N_NODES + 127) / 128)   /* 782 dst tiles */
#define NBK2    (NT * N_REL * 128)        /* 1601536 per-row buckets */
#define HS      132                       /* hA row stride (floats) */
#define BS      136                       /* B smem row stride (floats) */
#define HSZ     (128 * HS)                /* floats per hA buffer */

// smem: hA0 | hA1 | B-ring(3 x 32*BS) | bnd(8 warps x 20)
#define SMF_B    (2 * HSZ)
#define SMF_BND  (2 * HSZ + 3 * 32 * BS)
#define SMEM_FLOATS (SMF_BND + 8 * 20)
#define NSTG     (4 * NW)                 /* 68 B k-chunks */

// ---------------- device scratch ----------------
__device__ unsigned      g_emeta[N_REL * N_EDGES];   // src, sorted by (tile,rel,row)
__device__ float         g_B[NW * CH * CH];          // tf32-rounded weights
__device__ int           g_bcnt[NBK2];
__device__ int           g_boff[NBK2 + 1];
__device__ int           g_bfill[NBK2];
__device__ int           g_bsum[2048];
__device__ int           g_flags[2];

// ---------------- dtype detection (jax int64/bool layout may vary) -------
__global__ void k_detect(const unsigned* __restrict__ w, const unsigned char* __restrict__ mb) {
    __shared__ int s64, s32;
    if (threadIdx.x == 0) { s64 = 0; s32 = 0; }
    __syncthreads();
    if (threadIdx.x < 128) { if (w[2 * threadIdx.x + 1] != 0u) atomicAdd(&s64, 1); }
    if (threadIdx.x < 192) {
        int i = (threadIdx.x / 3) * 4 + 1 + (threadIdx.x % 3);
        if (mb[i] != 0) atomicAdd(&s32, 1);
    }
    __syncthreads();
    if (threadIdx.x == 0) { g_flags[0] = (s64 < 8); g_flags[1] = (s32 < 8); }
}

__device__ __forceinline__ int rd_idx(const void* p, int i) {
    return g_flags[0] ? (int)((const long long*)p)[i] : ((const int*)p)[i];
}
__device__ __forceinline__ int rd_mask(const void* p, int i) {
    return g_flags[1] ? (((const int*)p)[i] != 0) : (int)((const unsigned char*)p)[i];
}

// ---------------- zero bucket counts ----------------
__global__ void k_zero_pre() {
    int stride = gridDim.x * blockDim.x;
    for (int i = blockIdx.x * blockDim.x + threadIdx.x; i < NBK2; i += stride)
        g_bcnt[i] = 0;
}

// ---------------- per-row bucket counting (1 atomic/edge) ----------------
__global__ void k_deg(const void* __restrict__ idx, const void* __restrict__ mask) {
    int e = blockIdx.x * blockDim.x + threadIdx.x;
    int rel = blockIdx.y;
    if (e >= N_EDGES) return;
    if (!rd_mask(mask, rel * N_EDGES + e)) return;
    int dst = rd_idx(idx, rel * 2 * N_EDGES + N_EDGES + e);
    int key = ((dst >> 7) * N_REL + rel) * 128 + (dst & 127);
    atomicAdd(&g_bcnt[key], 1);
}

// ---------------- prefix scan over 1.6M (3 kernels) ----------------
__global__ void k_scan1() {      // 1564 blocks x 1024 (1564*1024 == NBK2)
    __shared__ int sh[1024];
    int i = blockIdx.x * 1024 + threadIdx.x;
    int v = g_bcnt[i];
    sh[threadIdx.x] = v;
    __syncthreads();
    for (int off = 1; off < 1024; off <<= 1) {
        int t = (threadIdx.x >= off) ? sh[threadIdx.x - off] : 0;
        __syncthreads();
        sh[threadIdx.x] += t;
        __syncthreads();
    }
    g_boff[i] = sh[threadIdx.x] - v;                 // local exclusive
    if (threadIdx.x == 1023) g_bsum[blockIdx.x] = sh[1023];
}

__global__ void k_scan2(int nb) {   // single block, capacity 2048
    __shared__ int sh[2048];
    int t = threadIdx.x;
    int v0 = (t < nb) ? g_bsum[t] : 0;
    int v1 = (t + 1024 < nb) ? g_bsum[t + 1024] : 0;
    sh[t] = v0; sh[t + 1024] = v1;
    __syncthreads();
    for (int off = 1; off < 2048; off <<= 1) {
        int a = (t >= off) ? sh[t - off] : 0;
        int b = (t + 1024 >= off) ? sh[t + 1024 - off] : 0;
        __syncthreads();
        sh[t] += a; sh[t + 1024] += b;
        __syncthreads();
    }
    if (t < nb) g_bsum[t] = sh[t] - v0;              // exclusive
    if (t + 1024 < nb) g_bsum[t + 1024] = sh[t + 1024] - v1;
    if (t == 0) g_boff[NBK2] = sh[2047];             // total
}

__global__ void k_scan3() {
    int i = blockIdx.x * 1024 + threadIdx.x;
    int o = g_boff[i] + g_bsum[blockIdx.x];
    g_boff[i] = o;
    g_bfill[i] = o;
}

// ---------------- fill sorted edge meta (src only) ----------------
__global__ void k_fill(const void* __restrict__ idx, const void* __restrict__ mask) {
    int e = blockIdx.x * blockDim.x + threadIdx.x;
    int rel = blockIdx.y;
    if (e >= N_EDGES) return;
    if (!rd_mask(mask, rel * N_EDGES + e)) return;
    int src = rd_idx(idx, rel * 2 * N_EDGES + e);
    int dst = rd_idx(idx, rel * 2 * N_EDGES + N_EDGES + e);
    int key = ((dst >> 7) * N_REL + rel) * 128 + (dst & 127);
    int pos = atomicAdd(&g_bfill[key], 1);
    g_emeta[pos] = (unsigned)src;
}

// ---------------- tf32-round weights ----------------
__device__ __forceinline__ unsigned f2tf(float f) {
    unsigned r;
    asm("cvt.rna.tf32.f32 %0, %1;" : "=r"(r) : "f"(f));
    return r;
}

__global__ void k_roundB(const float* __restrict__ selfw, const float* __restrict__ relw) {
    int i = blockIdx.x * blockDim.x + threadIdx.x;
    if (i >= NW * CH * CH) return;
    float v = (i < CH * CH) ? selfw[i] : relw[i - CH * CH];
    g_B[i] = __uint_as_float(f2tf(v));
}

// ---------------- fused kernel helpers (mma side identical to R6) --------
__device__ __forceinline__ void cp16(float* sdst, const float* gsrc) {
    unsigned s = (unsigned)__cvta_generic_to_shared(sdst);
    asm volatile("cp.async.cg.shared.global [%0], [%1], 16;\n" :: "r"(s), "l"(gsrc));
}

__device__ __forceinline__ void cp_stage(float* sB, int s, int tid) {
    if (s < NSTG) {
        int w = s >> 2, kt = s & 3;
        float* dB = sB + (s % 3) * 32 * BS;
        const float* src0 = g_B + (size_t)w * CH * CH + kt * 32 * CH;
#pragma unroll
        for (int i = 0; i < 4; i++) {
            int idx = tid + 256 * i;
            int kr = idx >> 5, c4 = idx & 31;
            cp16(dB + kr * BS + c4 * 4, src0 + kr * CH + c4 * 4);
        }
    }
    asm volatile("cp.async.commit_group;\n");   // uniform group count
}

__device__ __forceinline__ void mma4(float (*c)[4][4], const float* A, const float* Bsm,
                                     int lane) {
#pragma unroll
    for (int ks = 0; ks < 4; ks++) {
        unsigned a[4][4], b[4][2];
        int col = ks * 8 + (lane & 3);
        int r = lane >> 2;
#pragma unroll
        for (int mf = 0; mf < 4; mf++) {
            const float* Ap = A + (mf * 16 + r) * HS + col;
            a[mf][0] = f2tf(Ap[0]);
            a[mf][1] = f2tf(Ap[8 * HS]);
            a[mf][2] = f2tf(Ap[4]);
            a[mf][3] = f2tf(Ap[8 * HS + 4]);
        }
        int kr = ks * 8 + (lane & 3);
#pragma unroll
        for (int nf = 0; nf < 4; nf++) {
            const float* Bp = Bsm + kr * BS + nf * 8 + (lane >> 2);
            b[nf][0] = __float_as_uint(Bp[0]);       // pre-rounded tf32
            b[nf][1] = __float_as_uint(Bp[4 * BS]);
        }
#pragma unroll
        for (int mf = 0; mf < 4; mf++)
#pragma unroll
            for (int nf = 0; nf < 4; nf++)
                asm volatile(
                    "mma.sync.aligned.m16n8k8.row.col.f32.tf32.tf32.f32 "
                    "{%0,%1,%2,%3},{%4,%5,%6,%7},{%8,%9},{%0,%1,%2,%3};\n"
                    : "+f"(c[mf][nf][0]), "+f"(c[mf][nf][1]),
                      "+f"(c[mf][nf][2]), "+f"(c[mf][nf][3])
                    : "r"(a[mf][0]), "r"(a[mf][1]), "r"(a[mf][2]), "r"(a[mf][3]),
                      "r"(b[nf][0]), "r"(b[nf][1]));
    }
}

// gather warp gwid: rows [gwid*16, +16). Edges row-sorted & contiguous ->
// register accumulation, one store per row, scale = 1/count from offsets.
__device__ __forceinline__ void gather_rel(const float* __restrict__ x, float* hb,
                                           int* sbnd, int tile, int rel,
                                           int gwid, int lane) {
    int r0 = gwid * 16;
    int key0 = (tile * N_REL + rel) * 128 + r0;
    if (lane < 17) sbnd[lane] = __ldg(g_boff + key0 + lane);
    __syncwarp();

    int beg = sbnd[0], end = sbnd[16];
    int row = 0;
    int cur = sbnd[0], nxt = sbnd[1];
    float4 acc = make_float4(0.f, 0.f, 0.f, 0.f);

#define FLUSH_TO(P)                                                         \
    while (row < 16 && (P) >= nxt) {                                        \
        int cnt = nxt - cur;                                                \
        float s = (cnt > 0) ? (1.0f / (float)cnt) : 0.0f;                   \
        ((float4*)(hb + (r0 + row) * HS))[lane] =                           \
            make_float4(acc.x * s, acc.y * s, acc.z * s, acc.w * s);        \
        acc = make_float4(0.f, 0.f, 0.f, 0.f);                              \
        row++;                                                              \
        cur = nxt;                                                          \
        if (row < 16) nxt = sbnd[row + 1];                                  \
    }

    for (int base = beg; base < end; base += 32) {
        unsigned m = 0;
        if (base + lane < end) m = g_emeta[base + lane];
        int n = min(32, end - base);

        float4 v[8];
#pragma unroll
        for (int t = 0; t < 8; t++) {
            if (t < n) {
                int sc = __shfl_sync(0xffffffffu, m, t);
                v[t] = __ldg((const float4*)(x + (size_t)sc * CH) + lane);
            }
        }
        for (int j = 0; j < n; j += 8) {
#pragma unroll
            for (int t = 0; t < 8; t++) {
                if (j + t < n) {
                    FLUSH_TO(base + j + t);
                    acc.x += v[t].x; acc.y += v[t].y;
                    acc.z += v[t].z; acc.w += v[t].w;
                    int nx = j + 8 + t;
                    if (nx < n) {
                        int sc = __shfl_sync(0xffffffffu, m, nx);
                        v[t] = __ldg((const float4*)(x + (size_t)sc * CH) + lane);
                    }
                }
            }
        }
    }
    FLUSH_TO(end);   // finalize current + remaining (zero) rows
#undef FLUSH_TO
}

// ---------------- fused: warp-specialized (warps 0-7 mma, 8-15 gather) ---
__global__ __launch_bounds__(512, 1) void k_fused(const float* __restrict__ x,
                                                  float* __restrict__ out) {
    extern __shared__ float sm[];
    float* hA = sm;                 // 2 buffers
    float* sB = sm + SMF_B;         // 3-slot ring
    int*   sbndA = (int*)(sm + SMF_BND);
    int tid = threadIdx.x, wid = tid >> 5, lane = tid & 31;
    int tile = blockIdx.x, bM = tile * 128;
    bool is_mma = (wid < 8);

    float c[4][4][4];
#pragma unroll
    for (int i = 0; i < 4; i++)
#pragma unroll
        for (int j = 0; j < 4; j++)
#pragma unroll
            for (int k = 0; k < 4; k++) c[i][j][k] = 0.f;

    if (is_mma) {
        cp_stage(sB, 0, tid);
        cp_stage(sB, 1, tid);
    } else {
        // self tile (weight 0) = x rows -> hA[0]
        int gwid = wid - 8, r0 = gwid * 16;
#pragma unroll
        for (int r = 0; r < 16; r++) {
            int rg = bM + r0 + r;
            float4 v = make_float4(0.f, 0.f, 0.f, 0.f);
            if (rg < N_NODES) v = __ldg((const float4*)(x + (size_t)rg * CH) + lane);
            ((float4*)(hA + (r0 + r) * HS))[lane] = v;
        }
    }
    __syncthreads();   // hA[0] ready

#pragma unroll 1
    for (int w = 0; w < NW; w++) {
        if (is_mma) {
            int wm = wid >> 2, wn = wid & 3;     // 2x4 warp grid over 128x128
            const float* A = hA + (w & 1) * HSZ + (wm * 64) * HS;
#pragma unroll 1
            for (int kt = 0; kt < 4; kt++) {
                int s = w * 4 + kt;
                asm volatile("cp.async.wait_group 1;\n");         // stage s landed
                asm volatile("bar.sync 1, 256;\n" ::: "memory");  // mma copies done
                cp_stage(sB, s + 2, tid);        // slot (s-1)%3 free after bar
                mma4(c, A + kt * 32, sB + (s % 3) * 32 * BS + wn * 32, lane);
            }
        } else if (w < NW - 1) {
            int gwid = wid - 8;
            gather_rel(x, hA + ((w + 1) & 1) * HSZ, sbndA + gwid * 20,
                       tile, w, gwid, lane);
        }
        __syncthreads();   // weight boundary: next A ready, current A free
    }

    // epilogue (mma warps own the accumulators)
    if (is_mma) {
        int wm = wid >> 2, wn = wid & 3;
#pragma unroll
        for (int mf = 0; mf < 4; mf++) {
            int r0 = bM + wm * 64 + mf * 16 + (lane >> 2);
#pragma unroll
            for (int nf = 0; nf < 4; nf++) {
                int cc = wn * 32 + nf * 8 + (lane & 3) * 2;
                if (r0 < N_NODES)
                    *(float2*)(out + (size_t)r0 * CH + cc) =
                        make_float2(c[mf][nf][0], c[mf][nf][1]);
                if (r0 + 8 < N_NODES)
                    *(float2*)(out + (size_t)(r0 + 8) * CH + cc) =
                        make_float2(c[mf][nf][2], c[mf][nf][3]);
            }
        }
    }
}

// ---------------- launch ----------------
extern "C" void kernel_launch(void* const* d_in, const int* in_sizes, int n_in,
                              void* d_out, int out_size) {
    const float* x     = (const float*)d_in[0];
    const void*  idx   = d_in[1];
    const void*  mask  = d_in[2];
    const float* selfw = (const float*)d_in[3];
    const float* relw  = (const float*)d_in[4];
    float* out = (float*)d_out;

    static int init = 0;
    size_t smem = SMEM_FLOATS * sizeof(float);   // 188032 B
    if (!init) {
        cudaFuncSetAttribute(k_fused, cudaFuncAttributeMaxDynamicSharedMemorySize, (int)smem);
        init = 1;
    }

    int nb1 = NBK2 / 1024;   // 1564 (exact)

    k_detect<<<1, 256>>>((const unsigned*)idx, (const unsigned char*)mask);
    k_zero_pre<<<4096, 256>>>();
    k_roundB<<<(NW * CH * CH + 255) / 256, 256>>>(selfw, relw);
    k_deg<<<dim3((N_EDGES + 255) / 256, N_REL), 256>>>(idx, mask);
    k_scan1<<<nb1, 1024>>>();
    k_scan2<<<1, 1024>>>(nb1);
    k_scan3<<<nb1, 1024>>>();
    k_fill<<<dim3((N_EDGES + 255) / 256, N_REL), 256>>>(idx, mask);
    k_fused<<<NT, 512, smem>>>(x, out);
}

// round 10
// speedup vs baseline: 1.5462x; 1.5462x over previous
#include <cuda_runtime.h>
#include <cstdint>

#define N_NODES 100000
#define CH      128
#define N_REL   16
#define N_EDGES 200000
#define NW      17                        /* self + 16 relations */
#define NT      ((N_NODES + 127) / 128)   /* 782 dst tiles */
#define NBK     (NT * N_REL * 16)         /* 200192 buckets (tile,rel,8-row sub) */
#define HS      132                       /* hA row stride (floats) */
#define BS      136                       /* B smem row stride (floats) */
#define HSZ     (128 * HS)                /* floats per hA buffer */

// smem: hA0 | hA1 | B-ring(3 x 32*BS) | sub-bucket counters (16)
#define SMF_B    (2 * HSZ)
#define SMF_CTR  (2 * HSZ + 3 * 32 * BS)
#define SMEM_FLOATS (SMF_CTR + 16)
#define NSTG     (4 * NW)                 /* 68 B k-chunks */

// ---------------- device scratch ----------------
__device__ unsigned      g_emeta[N_REL * N_EDGES];   // src | dl<<17 (sorted by bucket)
__device__ float         g_B[NW * CH * CH];          // tf32-rounded weights
__device__ int           g_deg[N_REL * N_NODES];
__device__ float         g_invdeg[N_REL * N_NODES];
__device__ int           g_bcnt[NBK];
__device__ int           g_boff[NBK + 1];
__device__ int           g_bfill[NBK];
__device__ int           g_bsum[256];
__device__ int           g_flags[2];

// ---------------- dtype detection (jax int64/bool layout may vary) -------
__global__ void k_detect(const unsigned* __restrict__ w, const unsigned char* __restrict__ mb) {
    __shared__ int s64, s32;
    if (threadIdx.x == 0) { s64 = 0; s32 = 0; }
    __syncthreads();
    if (threadIdx.x < 128) { if (w[2 * threadIdx.x + 1] != 0u) atomicAdd(&s64, 1); }
    if (threadIdx.x < 192) {
        int i = (threadIdx.x / 3) * 4 + 1 + (threadIdx.x % 3);
        if (mb[i] != 0) atomicAdd(&s32, 1);
    }
    __syncthreads();
    if (threadIdx.x == 0) { g_flags[0] = (s64 < 8); g_flags[1] = (s32 < 8); }
}

__device__ __forceinline__ int rd_idx(const void* p, int i) {
    return g_flags[0] ? (int)((const long long*)p)[i] : ((const int*)p)[i];
}
__device__ __forceinline__ int rd_mask(const void* p, int i) {
    return g_flags[1] ? (((const int*)p)[i] != 0) : (int)((const unsigned char*)p)[i];
}

// ---------------- zero ----------------
__global__ void k_zero_pre() {
    int stride = gridDim.x * blockDim.x;
    for (int i = blockIdx.x * blockDim.x + threadIdx.x; i < N_REL * N_NODES; i += stride)
        g_deg[i] = 0;
    for (int i = blockIdx.x * blockDim.x + threadIdx.x; i < NBK; i += stride)
        g_bcnt[i] = 0;
}

// ---------------- degree + bucket counting ----------------
__global__ void k_deg(const void* __restrict__ idx, const void* __restrict__ mask) {
    int e = blockIdx.x * blockDim.x + threadIdx.x;
    int rel = blockIdx.y;
    if (e >= N_EDGES) return;
    if (!rd_mask(mask, rel * N_EDGES + e)) return;
    int dst = rd_idx(idx, rel * 2 * N_EDGES + N_EDGES + e);
    atomicAdd(&g_deg[rel * N_NODES + dst], 1);
    int key = ((dst >> 7) * N_REL + rel) * 16 + ((dst >> 3) & 15);
    atomicAdd(&g_bcnt[key], 1);
}

__global__ void k_invdeg() {
    int i = blockIdx.x * blockDim.x + threadIdx.x;
    if (i >= N_REL * N_NODES) return;
    int d = g_deg[i];
    g_invdeg[i] = d > 0 ? 1.0f / (float)d : 0.0f;
}

// ---------------- prefix scan ----------------
__global__ void k_scan1() {
    __shared__ int sh[1024];
    int i = blockIdx.x * 1024 + threadIdx.x;
    int v = (i < NBK) ? g_bcnt[i] : 0;
    sh[threadIdx.x] = v;
    __syncthreads();
    for (int off = 1; off < 1024; off <<= 1) {
        int t = (threadIdx.x >= off) ? sh[threadIdx.x - off] : 0;
        __syncthreads();
        sh[threadIdx.x] += t;
        __syncthreads();
    }
    if (i < NBK) g_boff[i] = sh[threadIdx.x] - v;
    if (threadIdx.x == 1023) g_bsum[blockIdx.x] = sh[1023];
}

__global__ void k_scan2(int nb) {
    __shared__ int sh[256];
    int v = (threadIdx.x < nb) ? g_bsum[threadIdx.x] : 0;
    sh[threadIdx.x] = v;
    __syncthreads();
    for (int off = 1; off < 256; off <<= 1) {
        int t = (threadIdx.x >= off) ? sh[threadIdx.x - off] : 0;
        __syncthreads();
        sh[threadIdx.x] += t;
        __syncthreads();
    }
    if (threadIdx.x < nb) g_bsum[threadIdx.x] = sh[threadIdx.x] - v;
    if (threadIdx.x == 255) g_boff[NBK] = sh[255];
}

__global__ void k_scan3() {
    int i = blockIdx.x * 1024 + threadIdx.x;
    if (i >= NBK) return;
    int o = g_boff[i] + g_bsum[blockIdx.x];
    g_boff[i] = o;
    g_bfill[i] = o;
}

// ---------------- fill sorted edge meta ----------------
__global__ void k_fill(const void* __restrict__ idx, const void* __restrict__ mask) {
    int e = blockIdx.x * blockDim.x + threadIdx.x;
    int rel = blockIdx.y;
    if (e >= N_EDGES) return;
    if (!rd_mask(mask, rel * N_EDGES + e)) return;
    int src = rd_idx(idx, rel * 2 * N_EDGES + e);
    int dst = rd_idx(idx, rel * 2 * N_EDGES + N_EDGES + e);
    int key = ((dst >> 7) * N_REL + rel) * 16 + ((dst >> 3) & 15);
    int pos = atomicAdd(&g_bfill[key], 1);
    g_emeta[pos] = (unsigned)src | ((unsigned)(dst & 127) << 17);
}

// ---------------- tf32-round weights ----------------
__device__ __forceinline__ unsigned f2tf(float f) {
    unsigned r;
    asm("cvt.rna.tf32.f32 %0, %1;" : "=r"(r) : "f"(f));
    return r;
}

__global__ void k_roundB(const float* __restrict__ selfw, const float* __restrict__ relw) {
    int i = blockIdx.x * blockDim.x + threadIdx.x;
    if (i >= NW * CH * CH) return;
    float v = (i < CH * CH) ? selfw[i] : relw[i - CH * CH];
    g_B[i] = __uint_as_float(f2tf(v));
}

// ---------------- fused kernel helpers ----------------
__device__ __forceinline__ void cp16(float* sdst, const float* gsrc) {
    unsigned s = (unsigned)__cvta_generic_to_shared(sdst);
    asm volatile("cp.async.cg.shared.global [%0], [%1], 16;\n" :: "r"(s), "l"(gsrc));
}

// B stage s (weight s>>2, k-chunk s&3) into ring slot s%3. mma threads (tid 0..255).
__device__ __forceinline__ void cp_stage(float* sB, int s, int tid) {
    if (s < NSTG) {
        int w = s >> 2, kt = s & 3;
        float* dB = sB + (s % 3) * 32 * BS;
        const float* src0 = g_B + (size_t)w * CH * CH + kt * 32 * CH;
#pragma unroll
        for (int i = 0; i < 4; i++) {
            int idx = tid + 256 * i;
            int kr = idx >> 5, c4 = idx & 31;
            cp16(dB + kr * BS + c4 * 4, src0 + kr * CH + c4 * 4);
        }
    }
    asm volatile("cp.async.commit_group;\n");   // uniform group count
}

// hA holds pre-rounded tf32 bits -> raw loads, no cvt on the mma path.
__device__ __forceinline__ void mma4(float (*c)[4][4], const float* A, const float* Bsm,
                                     int lane) {
#pragma unroll
    for (int ks = 0; ks < 4; ks++) {
        unsigned a[4][4], b[4][2];
        int col = ks * 8 + (lane & 3);
        int r = lane >> 2;
#pragma unroll
        for (int mf = 0; mf < 4; mf++) {
            const float* Ap = A + (mf * 16 + r) * HS + col;
            a[mf][0] = __float_as_uint(Ap[0]);
            a[mf][1] = __float_as_uint(Ap[8 * HS]);
            a[mf][2] = __float_as_uint(Ap[4]);
            a[mf][3] = __float_as_uint(Ap[8 * HS + 4]);
        }
        int kr = ks * 8 + (lane & 3);
#pragma unroll
        for (int nf = 0; nf < 4; nf++) {
            const float* Bp = Bsm + kr * BS + nf * 8 + (lane >> 2);
            b[nf][0] = __float_as_uint(Bp[0]);       // pre-rounded tf32
            b[nf][1] = __float_as_uint(Bp[4 * BS]);
        }
#pragma unroll
        for (int mf = 0; mf < 4; mf++)
#pragma unroll
            for (int nf = 0; nf < 4; nf++)
                asm volatile(
                    "mma.sync.aligned.m16n8k8.row.col.f32.tf32.tf32.f32 "
                    "{%0,%1,%2,%3},{%4,%5,%6,%7},{%8,%9},{%0,%1,%2,%3};\n"
                    : "+f"(c[mf][nf][0]), "+f"(c[mf][nf][1]),
                      "+f"(c[mf][nf][2]), "+f"(c[mf][nf][3])
                    : "r"(a[mf][0]), "r"(a[mf][1]), "r"(a[mf][2]), "r"(a[mf][3]),
                      "r"(b[nf][0]), "r"(b[nf][1]));
    }
}

// gather: 8 warps work-steal 16 sub-buckets (8 rows each) of relation rel.
// Raw-sum edges (R6's MLP-4 batching), then scale by invdeg + tf32-round the
// 8 owned rows at sub-bucket completion (rows are warp-private).
__device__ __forceinline__ void gather_rel(const float* __restrict__ x, float* hb,
                                           int* ctr, int tile, int rel, int lane) {
    const float* vd = g_invdeg + rel * N_NODES + tile * 128;
    for (;;) {
        int sb;
        if (lane == 0) sb = atomicAdd(ctr, 1);
        sb = __shfl_sync(0xffffffffu, sb, 0);
        if (sb >= 16) break;
        int r0 = sb * 8;

        float4 z = make_float4(0.f, 0.f, 0.f, 0.f);
#pragma unroll
        for (int r = 0; r < 8; r++)
            ((float4*)(hb + (r0 + r) * HS))[lane] = z;

        int key = (tile * N_REL + rel) * 16 + sb;
        int beg = __ldg(g_boff + key), end = __ldg(g_boff + key + 1);
        for (int base = beg; base < end; base += 32) {
            unsigned m = 0;
            if (base + lane < end) m = g_emeta[base + lane];
            int n = min(32, end - base);
            int j = 0;
            for (; j + 4 <= n; j += 4) {             // 4 independent 512B loads
                int dl[4], sn[4];
                float4 v[4];
#pragma unroll
                for (int t = 0; t < 4; t++) {
                    unsigned u = __shfl_sync(0xffffffffu, m, j + t);
                    sn[t] = (int)(u & 0x1FFFFu);
                    dl[t] = (int)(u >> 17);
                }
#pragma unroll
                for (int t = 0; t < 4; t++)
                    v[t] = __ldg((const float4*)(x + (size_t)sn[t] * CH) + lane);
#pragma unroll
                for (int t = 0; t < 4; t++) {
                    float4* hp = (float4*)(hb + dl[t] * HS) + lane;
                    float4 hv = *hp;
                    hv.x += v[t].x; hv.y += v[t].y;
                    hv.z += v[t].z; hv.w += v[t].w;
                    *hp = hv;
                }
            }
            for (; j < n; j++) {
                unsigned u = __shfl_sync(0xffffffffu, m, j);
                int sn = (int)(u & 0x1FFFFu);
                int dl = (int)(u >> 17);
                float4 v = __ldg((const float4*)(x + (size_t)sn * CH) + lane);
                float4* hp = (float4*)(hb + dl * HS) + lane;
                float4 hv = *hp;
                hv.x += v.x; hv.y += v.y; hv.z += v.z; hv.w += v.w;
                *hp = hv;
            }
        }

        // completion: scale by 1/deg + tf32-round the 8 rows (L1-hot)
        int nb = tile * 128 + r0;
#pragma unroll
        for (int r = 0; r < 8; r++) {
            float s = (nb + r < N_NODES) ? __ldg(vd + r0 + r) : 0.0f;
            float4* hp = (float4*)(hb + (r0 + r) * HS) + lane;
            float4 hv = *hp;
            uint4 t;
            t.x = f2tf(hv.x * s); t.y = f2tf(hv.y * s);
            t.z = f2tf(hv.z * s); t.w = f2tf(hv.w * s);
            *(uint4*)hp = t;
        }
    }
}

// ---------------- fused: warp-specialized (warps 0-7 mma, 8-15 gather) ---
__global__ __launch_bounds__(512, 1) void k_fused(const float* __restrict__ x,
                                                  float* __restrict__ out) {
    extern __shared__ float sm[];
    float* hA = sm;                 // 2 buffers
    float* sB = sm + SMF_B;         // 3-slot ring
    int*   ctr = (int*)(sm + SMF_CTR);
    int tid = threadIdx.x, wid = tid >> 5, lane = tid & 31;
    int tile = blockIdx.x, bM = tile * 128;
    bool is_mma = (wid < 8);

    if (tid < 16) ctr[tid] = 0;     // one claim counter per relation

    float c[4][4][4];
#pragma unroll
    for (int i = 0; i < 4; i++)
#pragma unroll
        for (int j = 0; j < 4; j++)
#pragma unroll
            for (int k = 0; k < 4; k++) c[i][j][k] = 0.f;

    if (is_mma) {
        cp_stage(sB, 0, tid);
        cp_stage(sB, 1, tid);
    } else {
        // self tile (weight 0) = x rows -> hA[0], tf32-rounded at write
        int gwid = wid - 8, r0 = gwid * 16;
#pragma unroll
        for (int r = 0; r < 16; r++) {
            int rg = bM + r0 + r;
            float4 v = make_float4(0.f, 0.f, 0.f, 0.f);
            if (rg < N_NODES) v = __ldg((const float4*)(x + (size_t)rg * CH) + lane);
            uint4 t;
            t.x = f2tf(v.x); t.y = f2tf(v.y); t.z = f2tf(v.z); t.w = f2tf(v.w);
            ((uint4*)(hA + (r0 + r) * HS))[lane] = t;
        }
    }
    __syncthreads();   // hA[0] + counters ready

#pragma unroll 1
    for (int w = 0; w < NW; w++) {
        if (is_mma) {
            int wm = wid >> 2, wn = wid & 3;     // 2x4 warp grid over 128x128
            const float* A = hA + (w & 1) * HSZ + (wm * 64) * HS;
#pragma unroll 1
            for (int kt = 0; kt < 4; kt++) {
                int s = w * 4 + kt;
                asm volatile("cp.async.wait_group 1;\n");         // stage s landed
                asm volatile("bar.sync 1, 256;\n" ::: "memory");  // mma copies done
                cp_stage(sB, s + 2, tid);        // slot (s-1)%3 free after bar
                mma4(c, A + kt * 32, sB + (s % 3) * 32 * BS + wn * 32, lane);
            }
        } else if (w < NW - 1) {
            // build hA[(w+1)&1] for relation w while mma chews on hA[w&1]
            gather_rel(x, hA + ((w + 1) & 1) * HSZ, ctr + w, tile, w, lane);
        }
        __syncthreads();   // weight boundary: next A ready, current A free
    }

    // epilogue (mma warps own the accumulators)
    if (is_mma) {
        int wm = wid >> 2, wn = wid & 3;
#pragma unroll
        for (int mf = 0; mf < 4; mf++) {
            int r0 = bM + wm * 64 + mf * 16 + (lane >> 2);
#pragma unroll
            for (int nf = 0; nf < 4; nf++) {
                int cc = wn * 32 + nf * 8 + (lane & 3) * 2;
                if (r0 < N_NODES)
                    *(float2*)(out + (size_t)r0 * CH + cc) =
                        make_float2(c[mf][nf][0], c[mf][nf][1]);
                if (r0 + 8 < N_NODES)
                    *(float2*)(out + (size_t)(r0 + 8) * CH + cc) =
                        make_float2(c[mf][nf][2], c[mf][nf][3]);
            }
        }
    }
}

// ---------------- launch ----------------
extern "C" void kernel_launch(void* const* d_in, const int* in_sizes, int n_in,
                              void* d_out, int out_size) {
    const float* x     = (const float*)d_in[0];
    const void*  idx   = d_in[1];
    const void*  mask  = d_in[2];
    const float* selfw = (const float*)d_in[3];
    const float* relw  = (const float*)d_in[4];
    float* out = (float*)d_out;

    static int init = 0;
    size_t smem = SMEM_FLOATS * sizeof(float);   // 187456 B
    if (!init) {
        cudaFuncSetAttribute(k_fused, cudaFuncAttributeMaxDynamicSharedMemorySize, (int)smem);
        init = 1;
    }

    int nb1 = (NBK + 1023) / 1024;   // 196

    k_detect<<<1, 256>>>((const unsigned*)idx, (const unsigned char*)mask);
    k_zero_pre<<<4096, 256>>>();
    k_roundB<<<(NW * CH * CH + 255) / 256, 256>>>(selfw, relw);
    k_deg<<<dim3((N_EDGES + 255) / 256, N_REL), 256>>>(idx, mask);
    k_invdeg<<<(N_REL * N_NODES + 255) / 256, 256>>>();
    k_scan1<<<nb1, 1024>>>();
    k_scan2<<<1, 256>>>(nb1);
    k_scan3<<<nb1, 1024>>>();
    k_fill<<<dim3((N_EDGES + 255) / 256, N_REL), 256>>>(idx, mask);
    k_fused<<<NT, 512, smem>>>(x, out);
}

// round 11
// speedup vs baseline: 1.8917x; 1.2235x over previous
#include <cuda_runtime.h>
#include <cstdint>

#define N_NODES 100000
#define CH      128
#define N_REL   16
#define N_EDGES 200000
#define NW      17                        /* self + 16 relations */
#define TM      64                        /* tile rows */
#define NT      ((N_NODES + TM - 1) / TM) /* 1563 dst tiles */
#define NBK     (NT * N_REL * 4)          /* 100032 buckets (tile,rel,gwarp) */
#define HS      132                       /* hA row stride (floats) */
#define BS      136                       /* B smem row stride (floats) */
#define HSZ     (TM * HS)                 /* 8448 floats per hA buffer */

// smem: hA0 | hA1 | B-ring(2 x 32*BS)
#define SMF_B    (2 * HSZ)
#define SMEM_FLOATS (SMF_B + 2 * 32 * BS)  /* 25600 floats = 102400 B */
#define NSTG     (4 * NW)                 /* 68 B k-chunks */

// ---------------- device scratch ----------------
__device__ unsigned      g_emeta[N_REL * N_EDGES];   // src | dl<<17 (sorted by bucket)
__device__ float         g_B[NW * CH * CH];          // tf32-rounded weights
__device__ int           g_deg[N_REL * N_NODES];
__device__ float         g_invdeg[N_REL * N_NODES];
__device__ int           g_bcnt[NBK];
__device__ int           g_boff[NBK + 1];
__device__ int           g_bfill[NBK];
__device__ int           g_bsum[128];
__device__ int           g_flags[2];

// ---------------- tf32 round ----------------
__device__ __forceinline__ unsigned f2tf(float f) {
    unsigned r;
    asm("cvt.rna.tf32.f32 %0, %1;" : "=r"(r) : "f"(f));
    return r;
}

// ---------------- prep0: detect dtypes + zero + round weights ------------
__global__ void k_prep0(const unsigned* __restrict__ w, const unsigned char* __restrict__ mb,
                        const float* __restrict__ selfw, const float* __restrict__ relw) {
    if (blockIdx.x == 0) {
        __shared__ int s64, s32;
        if (threadIdx.x == 0) { s64 = 0; s32 = 0; }
        __syncthreads();
        if (threadIdx.x < 128) { if (w[2 * threadIdx.x + 1] != 0u) atomicAdd(&s64, 1); }
        if (threadIdx.x < 192) {
            int i = (threadIdx.x / 3) * 4 + 1 + (threadIdx.x % 3);
            if (mb[i] != 0) atomicAdd(&s32, 1);
        }
        __syncthreads();
        if (threadIdx.x == 0) { g_flags[0] = (s64 < 8); g_flags[1] = (s32 < 8); }
    }
    int stride = gridDim.x * blockDim.x;
    int g = blockIdx.x * blockDim.x + threadIdx.x;
    for (int i = g; i < N_REL * N_NODES; i += stride) g_deg[i] = 0;
    for (int i = g; i < NBK; i += stride) g_bcnt[i] = 0;
    for (int i = g; i < NW * CH * CH; i += stride) {
        float v = (i < CH * CH) ? selfw[i] : relw[i - CH * CH];
        g_B[i] = __uint_as_float(f2tf(v));
    }
}

__device__ __forceinline__ int rd_idx(const void* p, int i) {
    return g_flags[0] ? (int)((const long long*)p)[i] : ((const int*)p)[i];
}
__device__ __forceinline__ int rd_mask(const void* p, int i) {
    return g_flags[1] ? (((const int*)p)[i] != 0) : (int)((const unsigned char*)p)[i];
}

// ---------------- degree + bucket counting ----------------
__global__ void k_deg(const void* __restrict__ idx, const void* __restrict__ mask) {
    int e = blockIdx.x * blockDim.x + threadIdx.x;
    int rel = blockIdx.y;
    if (e >= N_EDGES) return;
    if (!rd_mask(mask, rel * N_EDGES + e)) return;
    int dst = rd_idx(idx, rel * 2 * N_EDGES + N_EDGES + e);
    atomicAdd(&g_deg[rel * N_NODES + dst], 1);
    int key = ((dst >> 6) * N_REL + rel) * 4 + ((dst >> 4) & 3);
    atomicAdd(&g_bcnt[key], 1);
}

__global__ void k_invdeg() {
    int i = blockIdx.x * blockDim.x + threadIdx.x;
    if (i >= N_REL * N_NODES) return;
    int d = g_deg[i];
    g_invdeg[i] = d > 0 ? 1.0f / (float)d : 0.0f;
}

// ---------------- prefix scan ----------------
__global__ void k_scan1() {
    __shared__ int sh[1024];
    int i = blockIdx.x * 1024 + threadIdx.x;
    int v = (i < NBK) ? g_bcnt[i] : 0;
    sh[threadIdx.x] = v;
    __syncthreads();
    for (int off = 1; off < 1024; off <<= 1) {
        int t = (threadIdx.x >= off) ? sh[threadIdx.x - off] : 0;
        __syncthreads();
        sh[threadIdx.x] += t;
        __syncthreads();
    }
    if (i < NBK) g_boff[i] = sh[threadIdx.x] - v;
    if (threadIdx.x == 1023) g_bsum[blockIdx.x] = sh[1023];
}

__global__ void k_scan2(int nb) {
    __shared__ int sh[128];
    int v = (threadIdx.x < nb) ? g_bsum[threadIdx.x] : 0;
    sh[threadIdx.x] = v;
    __syncthreads();
    for (int off = 1; off < 128; off <<= 1) {
        int t = (threadIdx.x >= off) ? sh[threadIdx.x - off] : 0;
        __syncthreads();
        sh[threadIdx.x] += t;
        __syncthreads();
    }
    if (threadIdx.x < nb) g_bsum[threadIdx.x] = sh[threadIdx.x] - v;
    if (threadIdx.x == 127) g_boff[NBK] = sh[127];
}

__global__ void k_scan3() {
    int i = blockIdx.x * 1024 + threadIdx.x;
    if (i >= NBK) return;
    int o = g_boff[i] + g_bsum[blockIdx.x];
    g_boff[i] = o;
    g_bfill[i] = o;
}

// ---------------- fill sorted edge meta ----------------
__global__ void k_fill(const void* __restrict__ idx, const void* __restrict__ mask) {
    int e = blockIdx.x * blockDim.x + threadIdx.x;
    int rel = blockIdx.y;
    if (e >= N_EDGES) return;
    if (!rd_mask(mask, rel * N_EDGES + e)) return;
    int src = rd_idx(idx, rel * 2 * N_EDGES + e);
    int dst = rd_idx(idx, rel * 2 * N_EDGES + N_EDGES + e);
    int key = ((dst >> 6) * N_REL + rel) * 4 + ((dst >> 4) & 3);
    int pos = atomicAdd(&g_bfill[key], 1);
    g_emeta[pos] = (unsigned)src | ((unsigned)(dst & 63) << 17);
}

// ---------------- fused kernel helpers (inner code identical to R6) ------
__device__ __forceinline__ void cp16(float* sdst, const float* gsrc) {
    unsigned s = (unsigned)__cvta_generic_to_shared(sdst);
    asm volatile("cp.async.cg.shared.global [%0], [%1], 16;\n" :: "r"(s), "l"(gsrc));
}

// B stage s (weight s>>2, k-chunk s&3) into ring slot s&1. mma threads (tid 0..127).
__device__ __forceinline__ void cp_stage(float* sB, int s, int tid) {
    if (s < NSTG) {
        int w = s >> 2, kt = s & 3;
        float* dB = sB + (s & 1) * 32 * BS;
        const float* src0 = g_B + (size_t)w * CH * CH + kt * 32 * CH;
#pragma unroll
        for (int i = 0; i < 8; i++) {
            int idx = tid + 128 * i;
            int kr = idx >> 5, c4 = idx & 31;
            cp16(dB + kr * BS + c4 * 4, src0 + kr * CH + c4 * 4);
        }
    }
    asm volatile("cp.async.commit_group;\n");   // uniform group count
}

__device__ __forceinline__ void mma4(float (*c)[4][4], const float* A, const float* Bsm,
                                     int lane) {
#pragma unroll
    for (int ks = 0; ks < 4; ks++) {
        unsigned a[4][4], b[4][2];
        int col = ks * 8 + (lane & 3);
        int r = lane >> 2;
#pragma unroll
        for (int mf = 0; mf < 4; mf++) {
            const float* Ap = A + (mf * 16 + r) * HS + col;
            a[mf][0] = f2tf(Ap[0]);
            a[mf][1] = f2tf(Ap[8 * HS]);
            a[mf][2] = f2tf(Ap[4]);
            a[mf][3] = f2tf(Ap[8 * HS + 4]);
        }
        int kr = ks * 8 + (lane & 3);
#pragma unroll
        for (int nf = 0; nf < 4; nf++) {
            const float* Bp = Bsm + kr * BS + nf * 8 + (lane >> 2);
            b[nf][0] = __float_as_uint(Bp[0]);       // pre-rounded tf32
            b[nf][1] = __float_as_uint(Bp[4 * BS]);
        }
#pragma unroll
        for (int mf = 0; mf < 4; mf++)
#pragma unroll
            for (int nf = 0; nf < 4; nf++)
                asm volatile(
                    "mma.sync.aligned.m16n8k8.row.col.f32.tf32.tf32.f32 "
                    "{%0,%1,%2,%3},{%4,%5,%6,%7},{%8,%9},{%0,%1,%2,%3};\n"
                    : "+f"(c[mf][nf][0]), "+f"(c[mf][nf][1]),
                      "+f"(c[mf][nf][2]), "+f"(c[mf][nf][3])
                    : "r"(a[mf][0]), "r"(a[mf][1]), "r"(a[mf][2]), "r"(a[mf][3]),
                      "r"(b[nf][0]), "r"(b[nf][1]));
    }
}

// gather warp gwid: rows [gwid*16, gwid*16+16) = sum x[src]*invdeg (R6 code, MLP-4)
__device__ __forceinline__ void gather_rel(const float* __restrict__ x, float* hb,
                                           int tile, int rel, int gwid, int lane) {
    float4 z = make_float4(0.f, 0.f, 0.f, 0.f);
    int r0 = gwid * 16;
#pragma unroll
    for (int r = 0; r < 16; r++)
        ((float4*)(hb + (r0 + r) * HS))[lane] = z;

    int key = (tile * N_REL + rel) * 4 + gwid;
    int beg = g_boff[key], end = g_boff[key + 1];
    const float* vd = g_invdeg + rel * N_NODES + tile * TM;
    for (int base = beg; base < end; base += 32) {
        unsigned m = 0;
        if (base + lane < end) m = g_emeta[base + lane];
        int n = min(32, end - base);
        int j = 0;
        for (; j + 4 <= n; j += 4) {                 // 4 independent 512B loads in flight
            int dl[4], sn[4];
            float sc[4];
            float4 v[4];
#pragma unroll
            for (int t = 0; t < 4; t++) {
                unsigned u = __shfl_sync(0xffffffffu, m, j + t);
                sn[t] = (int)(u & 0x1FFFFu);
                dl[t] = (int)(u >> 17);
            }
#pragma unroll
            for (int t = 0; t < 4; t++) sc[t] = __ldg(vd + dl[t]);
#pragma unroll
            for (int t = 0; t < 4; t++)
                v[t] = __ldg((const float4*)(x + (size_t)sn[t] * CH) + lane);
#pragma unroll
            for (int t = 0; t < 4; t++) {
                float4* hp = (float4*)(hb + dl[t] * HS) + lane;
                float4 hv = *hp;
                hv.x += v[t].x * sc[t]; hv.y += v[t].y * sc[t];
                hv.z += v[t].z * sc[t]; hv.w += v[t].w * sc[t];
                *hp = hv;
            }
        }
        for (; j < n; j++) {
            unsigned u = __shfl_sync(0xffffffffu, m, j);
            int sn = (int)(u & 0x1FFFFu);
            int dl = (int)(u >> 17);
            float s = __ldg(vd + dl);
            float4 v = __ldg((const float4*)(x + (size_t)sn * CH) + lane);
            float4* hp = (float4*)(hb + dl * HS) + lane;
            float4 hv = *hp;
            hv.x += v.x * s; hv.y += v.y * s; hv.z += v.z * s; hv.w += v.w * s;
            *hp = hv;
        }
    }
}

// ---------------- fused: 64-row tiles, warps 0-3 mma, 4-7 gather, 2 CTA/SM
__global__ __launch_bounds__(256, 2) void k_fused(const float* __restrict__ x,
                                                  float* __restrict__ out) {
    extern __shared__ float sm[];
    float* hA = sm;                 // 2 buffers
    float* sB = sm + SMF_B;         // 2-slot ring
    int tid = threadIdx.x, wid = tid >> 5, lane = tid & 31;
    int tile = blockIdx.x, bM = tile * TM;
    bool is_mma = (wid < 4);

    float c[4][4][4];
#pragma unroll
    for (int i = 0; i < 4; i++)
#pragma unroll
        for (int j = 0; j < 4; j++)
#pragma unroll
            for (int k = 0; k < 4; k++) c[i][j][k] = 0.f;

    if (is_mma) {
        cp_stage(sB, 0, tid);       // preload stage 0
    } else {
        // self tile (weight 0) = x rows -> hA[0]
        int gwid = wid - 4, r0 = gwid * 16;
#pragma unroll
        for (int r = 0; r < 16; r++) {
            int rg = bM + r0 + r;
            float4 v = make_float4(0.f, 0.f, 0.f, 0.f);
            if (rg < N_NODES) v = __ldg((const float4*)(x + (size_t)rg * CH) + lane);
            ((float4*)(hA + (r0 + r) * HS))[lane] = v;
        }
    }
    __syncthreads();   // hA[0] ready

#pragma unroll 1
    for (int w = 0; w < NW; w++) {
        if (is_mma) {
            int wn = wid;                          // 1x4 warp grid over 64x128
            const float* A = hA + (w & 1) * HSZ;
#pragma unroll 1
            for (int kt = 0; kt < 4; kt++) {
                int s = w * 4 + kt;
                asm volatile("cp.async.wait_group 0;\n");         // stage s landed
                asm volatile("bar.sync 1, 128;\n" ::: "memory");  // mma copies/reads done
                cp_stage(sB, s + 1, tid);          // slot (s+1)&1: readers done at bar
                mma4(c, A + kt * 32, sB + (s & 1) * 32 * BS + wn * 32, lane);
            }
        } else if (w < NW - 1) {
            // build hA[(w+1)&1] for relation w while mma chews on hA[w&1]
            gather_rel(x, hA + ((w + 1) & 1) * HSZ, tile, w, wid - 4, lane);
        }
        __syncthreads();   // weight boundary: next A ready, current A free
    }

    // epilogue (mma warps own the accumulators)
    if (is_mma) {
        int wn = wid;
#pragma unroll
        for (int mf = 0; mf < 4; mf++) {
            int r0 = bM + mf * 16 + (lane >> 2);
#pragma unroll
            for (int nf = 0; nf < 4; nf++) {
                int cc = wn * 32 + nf * 8 + (lane & 3) * 2;
                if (r0 < N_NODES)
                    *(float2*)(out + (size_t)r0 * CH + cc) =
                        make_float2(c[mf][nf][0], c[mf][nf][1]);
                if (r0 + 8 < N_NODES)
                    *(float2*)(out + (size_t)(r0 + 8) * CH + cc) =
                        make_float2(c[mf][nf][2], c[mf][nf][3]);
            }
        }
    }
}

// ---------------- launch ----------------
extern "C" void kernel_launch(void* const* d_in, const int* in_sizes, int n_in,
                              void* d_out, int out_size) {
    const float* x     = (const float*)d_in[0];
    const void*  idx   = d_in[1];
    const void*  mask  = d_in[2];
    const float* selfw = (const float*)d_in[3];
    const float* relw  = (const float*)d_in[4];
    float* out = (float*)d_out;

    static int init = 0;
    size_t smem = SMEM_FLOATS * sizeof(float);   // 102400 B
    if (!init) {
        cudaFuncSetAttribute(k_fused, cudaFuncAttributeMaxDynamicSharedMemorySize, (int)smem);
        init = 1;
    }

    int nb1 = (NBK + 1023) / 1024;   // 98

    k_prep0<<<4096, 256>>>((const unsigned*)idx, (const unsigned char*)mask, selfw, relw);
    k_deg<<<dim3((N_EDGES + 255) / 256, N_REL), 256>>>(idx, mask);
    k_invdeg<<<(N_REL * N_NODES + 255) / 256, 256>>>();
    k_scan1<<<nb1, 1024>>>();
    k_scan2<<<1, 128>>>(nb1);
    k_scan3<<<nb1, 1024>>>();
    k_fill<<<dim3((N_EDGES + 255) / 256, N_REL), 256>>>(idx, mask);
    k_fused<<<NT, 256, smem>>>(x, out);
}